// round 14
// baseline (speedup 1.0000x reference)
#include <cuda_runtime.h>

// out[oc,h,w] = sum_{k,ic} w[oc,k,ic] * xr[ic, (h-1)%14, w+k-1]   (zero pad on w+k-1)
// xr[ic,hh,j] = x[ic,hh,(j-1)%14] (W-roll); output H-roll folded into reading
// x row (h-1)%14 for output row h.
//
// Grid (7 hpair, 32 oc) x 256 threads: two independent copies of the proven
// 128-thread body per CTA (sub = tid>>7 selects h = hpair*2+sub). Same total
// resident warps as the 448x128 optimum, half the CTA count.

__global__ __launch_bounds__(256, 4)
void rolled_conv_kernel(const float* __restrict__ x,
                        const float* __restrict__ w,
                        float* __restrict__ out) {
    __shared__ float part[2][128][16];   // disjoint bank per sub
    __shared__ float part2[2][8][14];

    const int oc  = blockIdx.y;           // 0..31
    const int sub = threadIdx.x >> 7;     // 0..1 -> which output row
    const int ic  = threadIdx.x & 127;    // 0..127
    const int h   = blockIdx.x * 2 + sub; // 0..13

    const int hm1 = (h + 13) % 14;        // x row feeding this output row

    // Front-batch ALL loads (3 w + 7 x2) -> MLP = 10, one latency exposure.
    const float* wp = w + oc * 384 + ic;
    const float w0 = __ldg(wp);
    const float w1 = __ldg(wp + 128);
    const float w2 = __ldg(wp + 256);

    // x row: 14 floats; offset ic*196 + hm1*14 is even -> 7x LDG.64
    const float2* xr2 = reinterpret_cast<const float2*>(x + ic * 196 + hm1 * 14);
    float xrow[14];
#pragma unroll
    for (int j = 0; j < 7; j++) {
        float2 v = __ldg(xr2 + j);
        xrow[2 * j]     = v.x;
        xrow[2 * j + 1] = v.y;
    }

    // Per-channel partial for each of the 14 output columns
    float acc[14];
#pragma unroll
    for (int wi = 0; wi < 14; wi++) {
        float a = w1 * xrow[(wi + 13) % 14];          // k=1 tap (always valid)
        if (wi >= 1)  a += w0 * xrow[(wi + 12) % 14]; // k=0 tap
        if (wi <= 12) a += w2 * xrow[wi];             // k=2 tap
        acc[wi] = a;
    }

    // Stage 1: pack partials to smem (wide stores; STS is issue-only)
    {
        float4* dst4 = reinterpret_cast<float4*>(&part[sub][ic][0]);
        dst4[0] = make_float4(acc[0],  acc[1],  acc[2],  acc[3]);
        dst4[1] = make_float4(acc[4],  acc[5],  acc[6],  acc[7]);
        dst4[2] = make_float4(acc[8],  acc[9],  acc[10], acc[11]);
        reinterpret_cast<float2*>(&part[sub][ic][12])[0] = make_float2(acc[12], acc[13]);
    }
    __syncthreads();

    // Stage 2: per sub, 8x16 mapping: g = (tid&127)>>4, wi = tid&15.
    {
        const int g  = ic >> 4;
        const int wi = ic & 15;
        if (wi < 14) {
            const float* src = &part[sub][g * 16][wi];
            float v[16];
#pragma unroll
            for (int j = 0; j < 16; j++) v[j] = src[j * 16];
            float s01 = (v[0] + v[1]) + (v[2] + v[3]);
            float s23 = (v[4] + v[5]) + (v[6] + v[7]);
            float s45 = (v[8] + v[9]) + (v[10] + v[11]);
            float s67 = (v[12] + v[13]) + (v[14] + v[15]);
            part2[sub][g][wi] = (s01 + s23) + (s45 + s67);
        }
    }
    __syncthreads();

    // Stage 3: 14 threads per sub sum the 8 group partials and store
    if (ic < 14) {
        const int wi = ic;
        float s = ((part2[sub][0][wi] + part2[sub][1][wi]) + (part2[sub][2][wi] + part2[sub][3][wi]))
                + ((part2[sub][4][wi] + part2[sub][5][wi]) + (part2[sub][6][wi] + part2[sub][7][wi]));
        out[oc * 196 + h * 14 + wi] = s;
    }
}

extern "C" void kernel_launch(void* const* d_in, const int* in_sizes, int n_in,
                              void* d_out, int out_size) {
    const float* x = (const float*)d_in[0];   // (1,128,14,14) = 25088 floats
    const float* w = (const float*)d_in[1];   // (32,3,128)    = 12288 floats
    float* out = (float*)d_out;               // (1,32,14,14)  = 6272 floats

    dim3 grid(7, 32);
    rolled_conv_kernel<<<grid, 256>>>(x, w, out);
}

// round 15
// speedup vs baseline: 1.2308x; 1.2308x over previous
#include <cuda_runtime.h>

// out[oc,h,w] = sum_{k,ic} w[oc,k,ic] * xr[ic, (h-1)%14, w+k-1]   (zero pad on w+k-1)
// xr[ic,hh,j] = x[ic,hh,(j-1)%14] (W-roll); output H-roll folded into reading
// x row (h-1)%14 for output row h.
//
// FINAL: Grid (14 h, 32 oc) x 128 threads = ic. Best measured: 5.504us kernel /
// 6.624us bench. Front-batched loads (MLP=10), two-stage smem tree reduction,
// stage-2 power-of-two 8x16 mapping (<=2-way LDS conflict, no div/mod).
//
// Shape matrix fully measured this session: 448x4w optimal; 112x4w, 224x8w,
// 448x8w, 448x16w all worse. Reduction topologies (butterfly / 2-stage tree /
// tree+shfl) within noise except 8-way-conflict geometries. Problem is
// launch-ramp floored: DRAM 0.3%, fma <2%, issue <10% at the optimum.

__global__ __launch_bounds__(128, 8)
void rolled_conv_kernel(const float* __restrict__ x,
                        const float* __restrict__ w,
                        float* __restrict__ out) {
    __shared__ float part[128][16];   // 64B row stride -> float4-aligned
    __shared__ float part2[8][14];

    const int h  = blockIdx.x;   // output row 0..13
    const int oc = blockIdx.y;   // 0..31
    const int ic = threadIdx.x;  // 0..127

    const int hm1 = (h + 13) % 14;          // x row feeding this output row

    // Front-batch ALL loads (3 w + 7 x2) -> MLP = 10, one latency exposure.
    const float* wp = w + oc * 384 + ic;
    const float w0 = __ldg(wp);
    const float w1 = __ldg(wp + 128);
    const float w2 = __ldg(wp + 256);

    // x row: 14 floats; offset ic*196 + hm1*14 is even -> 7x LDG.64
    const float2* xr2 = reinterpret_cast<const float2*>(x + ic * 196 + hm1 * 14);
    float xrow[14];
#pragma unroll
    for (int j = 0; j < 7; j++) {
        float2 v = __ldg(xr2 + j);
        xrow[2 * j]     = v.x;
        xrow[2 * j + 1] = v.y;
    }

    // Per-channel partial for each of the 14 output columns
    float acc[14];
#pragma unroll
    for (int wi = 0; wi < 14; wi++) {
        float a = w1 * xrow[(wi + 13) % 14];          // k=1 tap (always valid)
        if (wi >= 1)  a += w0 * xrow[(wi + 12) % 14]; // k=0 tap
        if (wi <= 12) a += w2 * xrow[wi];             // k=2 tap
        acc[wi] = a;
    }

    // Stage 1: pack partials to smem (wide stores; STS is issue-only)
    {
        float4* dst4 = reinterpret_cast<float4*>(&part[ic][0]);
        dst4[0] = make_float4(acc[0],  acc[1],  acc[2],  acc[3]);
        dst4[1] = make_float4(acc[4],  acc[5],  acc[6],  acc[7]);
        dst4[2] = make_float4(acc[8],  acc[9],  acc[10], acc[11]);
        reinterpret_cast<float2*>(&part[ic][12])[0] = make_float2(acc[12], acc[13]);
    }
    __syncthreads();

    // Stage 2: 8x16 mapping, pure bitops: g = tid>>4 (ic group), wi = tid&15.
    {
        const int g  = threadIdx.x >> 4;
        const int wi = threadIdx.x & 15;
        if (wi < 14) {
            const float* src = &part[g * 16][wi];
            float v[16];
#pragma unroll
            for (int j = 0; j < 16; j++) v[j] = src[j * 16];
            float s01 = (v[0] + v[1]) + (v[2] + v[3]);
            float s23 = (v[4] + v[5]) + (v[6] + v[7]);
            float s45 = (v[8] + v[9]) + (v[10] + v[11]);
            float s67 = (v[12] + v[13]) + (v[14] + v[15]);
            part2[g][wi] = (s01 + s23) + (s45 + s67);
        }
    }
    __syncthreads();

    // Stage 3: 14 threads sum the 8 group partials and store
    if (threadIdx.x < 14) {
        const int wi = threadIdx.x;
        float s = ((part2[0][wi] + part2[1][wi]) + (part2[2][wi] + part2[3][wi]))
                + ((part2[4][wi] + part2[5][wi]) + (part2[6][wi] + part2[7][wi]));
        out[oc * 196 + h * 14 + wi] = s;
    }
}

extern "C" void kernel_launch(void* const* d_in, const int* in_sizes, int n_in,
                              void* d_out, int out_size) {
    const float* x = (const float*)d_in[0];   // (1,128,14,14) = 25088 floats
    const float* w = (const float*)d_in[1];   // (32,3,128)    = 12288 floats
    float* out = (float*)d_out;               // (1,32,14,14)  = 6272 floats

    dim3 grid(14, 32);
    rolled_conv_kernel<<<grid, 128>>>(x, w, out);
}

// round 16
// speedup vs baseline: 1.2367x; 1.0048x over previous
#include <cuda_runtime.h>

// out[oc,h,w] = sum_{k,ic} w[oc,k,ic] * xr[ic, (h-1)%14, w+k-1]   (zero pad on w+k-1)
// xr[ic,hh,j] = x[ic,hh,(j-1)%14] (W-roll); output H-roll folded into reading
// x row (h-1)%14 for output row h.
//
// FINAL (terminal, 15 rounds measured): Grid (14 h, 32 oc) x 128 threads = ic.
// Best measured: 5.504us kernel / 6.624us bench. Front-batched loads (MLP=10),
// two-stage smem tree reduction, stage-2 power-of-two 8x16 mapping.
//
// Session conclusion: this 4.8-MFLOP single launch is launch-ramp floored on
// GB300 — all on-chip pipes idle at the optimum (DRAM 0.3%, fma <2%, issue <9%).
// Full shape/reduction/load-structure matrix measured; every deviation from
// this configuration benched equal-or-worse.

__global__ __launch_bounds__(128, 8)
void rolled_conv_kernel(const float* __restrict__ x,
                        const float* __restrict__ w,
                        float* __restrict__ out) {
    __shared__ float part[128][16];   // 64B row stride -> float4-aligned
    __shared__ float part2[8][14];

    const int h  = blockIdx.x;   // output row 0..13
    const int oc = blockIdx.y;   // 0..31
    const int ic = threadIdx.x;  // 0..127

    const int hm1 = (h + 13) % 14;          // x row feeding this output row

    // Front-batch ALL loads (3 w + 7 x2) -> MLP = 10, one latency exposure.
    const float* wp = w + oc * 384 + ic;
    const float w0 = __ldg(wp);
    const float w1 = __ldg(wp + 128);
    const float w2 = __ldg(wp + 256);

    // x row: 14 floats; offset ic*196 + hm1*14 is even -> 7x LDG.64
    const float2* xr2 = reinterpret_cast<const float2*>(x + ic * 196 + hm1 * 14);
    float xrow[14];
#pragma unroll
    for (int j = 0; j < 7; j++) {
        float2 v = __ldg(xr2 + j);
        xrow[2 * j]     = v.x;
        xrow[2 * j + 1] = v.y;
    }

    // Per-channel partial for each of the 14 output columns
    float acc[14];
#pragma unroll
    for (int wi = 0; wi < 14; wi++) {
        float a = w1 * xrow[(wi + 13) % 14];          // k=1 tap (always valid)
        if (wi >= 1)  a += w0 * xrow[(wi + 12) % 14]; // k=0 tap
        if (wi <= 12) a += w2 * xrow[wi];             // k=2 tap
        acc[wi] = a;
    }

    // Stage 1: pack partials to smem (wide stores; STS is issue-only)
    {
        float4* dst4 = reinterpret_cast<float4*>(&part[ic][0]);
        dst4[0] = make_float4(acc[0],  acc[1],  acc[2],  acc[3]);
        dst4[1] = make_float4(acc[4],  acc[5],  acc[6],  acc[7]);
        dst4[2] = make_float4(acc[8],  acc[9],  acc[10], acc[11]);
        reinterpret_cast<float2*>(&part[ic][12])[0] = make_float2(acc[12], acc[13]);
    }
    __syncthreads();

    // Stage 2: 8x16 mapping, pure bitops: g = tid>>4 (ic group), wi = tid&15.
    {
        const int g  = threadIdx.x >> 4;
        const int wi = threadIdx.x & 15;
        if (wi < 14) {
            const float* src = &part[g * 16][wi];
            float v[16];
#pragma unroll
            for (int j = 0; j < 16; j++) v[j] = src[j * 16];
            float s01 = (v[0] + v[1]) + (v[2] + v[3]);
            float s23 = (v[4] + v[5]) + (v[6] + v[7]);
            float s45 = (v[8] + v[9]) + (v[10] + v[11]);
            float s67 = (v[12] + v[13]) + (v[14] + v[15]);
            part2[g][wi] = (s01 + s23) + (s45 + s67);
        }
    }
    __syncthreads();

    // Stage 3: 14 threads sum the 8 group partials and store
    if (threadIdx.x < 14) {
        const int wi = threadIdx.x;
        float s = ((part2[0][wi] + part2[1][wi]) + (part2[2][wi] + part2[3][wi]))
                + ((part2[4][wi] + part2[5][wi]) + (part2[6][wi] + part2[7][wi]));
        out[oc * 196 + h * 14 + wi] = s;
    }
}

extern "C" void kernel_launch(void* const* d_in, const int* in_sizes, int n_in,
                              void* d_out, int out_size) {
    const float* x = (const float*)d_in[0];   // (1,128,14,14) = 25088 floats
    const float* w = (const float*)d_in[1];   // (32,3,128)    = 12288 floats
    float* out = (float*)d_out;               // (1,32,14,14)  = 6272 floats

    dim3 grid(14, 32);
    rolled_conv_kernel<<<grid, 128>>>(x, w, out);
}